// round 7
// baseline (speedup 1.0000x reference)
#include <cuda_runtime.h>
#include <cuda_bf16.h>
#include <math.h>
#include <stdint.h>

// x[8,2048,1024] fp32, prototypes[64,1024] fp32, attn_mask[8,2048] int32.
#define DDIM 1024
#define NEXP 64
#define SEQ  2048
#define TM   128
#define KC   64
#define NCHUNK (DDIM / KC)
#define NT   128
#define MAXTOK 16384

// smem layout: padded rows, 144 bytes (36 words; 36 mod 32 = 4 -> conflict-free
// fragment LDS: bank = 4*row + c is injective over row 0..7, c 0..3).
#define RSTRIDE 144
#define A_BYTES (TM * RSTRIDE)            // 18432 per split
#define B_BYTES (NEXP * RSTRIDE)          // 9216 per split
#define AH_OFF 0
#define AM_OFF (A_BYTES)
#define AL_OFF (2 * A_BYTES)
#define BH_OFF (3 * A_BYTES)
#define BM_OFF (3 * A_BYTES + B_BYTES)
#define BL_OFF (3 * A_BYTES + 2 * B_BYTES)
#define BUFSZ  (3 * A_BYTES + 3 * B_BYTES)   // 82944
#define SMEM_INORM 0
#define SMEM_BUF0  1024
#define SMEM_TOTAL (SMEM_BUF0 + 2 * BUFSZ)   // 166912

__device__ float g_logits[MAXTOK * NEXP];
__device__ __nv_bfloat16 g_ph[NEXP * DDIM];
__device__ __nv_bfloat16 g_pm[NEXP * DDIM];
__device__ __nv_bfloat16 g_pl[NEXP * DDIM];

// ---------------- helpers ----------------
__device__ __forceinline__ void split3(float x, __nv_bfloat16& h,
                                       __nv_bfloat16& m, __nv_bfloat16& l) {
    h = __float2bfloat16(x);
    float r = x - __bfloat162float(h);
    m = __float2bfloat16(r);
    float r2 = r - __bfloat162float(m);
    l = __float2bfloat16(r2);
}
__device__ __forceinline__ uint32_t packbf(__nv_bfloat16 a, __nv_bfloat16 b) {
    __nv_bfloat162 v(a, b);
    return *reinterpret_cast<uint32_t*>(&v);
}
__device__ __forceinline__ void mma_bf16(float* d, const uint32_t* a,
                                         uint32_t b0, uint32_t b1) {
    asm volatile(
        "mma.sync.aligned.m16n8k16.row.col.f32.bf16.bf16.f32 "
        "{%0,%1,%2,%3}, {%4,%5,%6,%7}, {%8,%9}, {%0,%1,%2,%3};"
        : "+f"(d[0]), "+f"(d[1]), "+f"(d[2]), "+f"(d[3])
        : "r"(a[0]), "r"(a[1]), "r"(a[2]), "r"(a[3]), "r"(b0), "r"(b1));
}

// ---------------------------------------------------------------------------
// Kernel 0: split prototypes into bf16 h/m/l.
// ---------------------------------------------------------------------------
__global__ void proto_split_kernel(const float* __restrict__ p) {
    int i = blockIdx.x * blockDim.x + threadIdx.x;
    if (i < NEXP * DDIM) {
        __nv_bfloat16 h, m, l;
        split3(p[i], h, m, l);
        g_ph[i] = h; g_pm[i] = m; g_pl[i] = l;
    }
}

// ---------------------------------------------------------------------------
// Kernel 1: bf16x6 emulated-fp32 GEMM on tensor cores (mma.sync) + fused norm.
// 128 tokens x 64 experts per CTA; 4 warps, 32 tokens (2 m16-tiles) per warp.
// ---------------------------------------------------------------------------
__global__ __launch_bounds__(NT, 1) void gemm_kernel(const float* __restrict__ x) {
    extern __shared__ char smem[];
    float* inorm = reinterpret_cast<float*>(smem + SMEM_INORM);
    char* buf0 = smem + SMEM_BUF0;

    const int t = threadIdx.x;
    const int wid = t >> 5, lane = t & 31;
    const int r = lane >> 2, cq = lane & 3;
    const size_t blockRow = (size_t)blockIdx.x * TM;

    float acc[2][8][4];
#pragma unroll
    for (int i = 0; i < 2; i++)
#pragma unroll
        for (int j = 0; j < 8; j++)
#pragma unroll
            for (int q = 0; q < 4; q++) acc[i][j][q] = 0.f;

    float srow = 0.f;
    float4 va[16];
    const float4* xrow = reinterpret_cast<const float4*>(x + (blockRow + t) * DDIM);
#pragma unroll
    for (int i = 0; i < 16; i++) va[i] = xrow[i];

    const int brow = t & 63, bhalf = t >> 6;

    for (int c = 0; c < NCHUNK; c++) {
        char* buf = buf0 + (c & 1) * BUFSZ;
        const int kc = c * KC;

        // ---- stage B (h/m/l) from gmem: 4x uint4 per split per thread ----
        {
            const uint4* sh = reinterpret_cast<const uint4*>(g_ph + brow * DDIM + kc + bhalf * 32);
            const uint4* sm = reinterpret_cast<const uint4*>(g_pm + brow * DDIM + kc + bhalf * 32);
            const uint4* sl = reinterpret_cast<const uint4*>(g_pl + brow * DDIM + kc + bhalf * 32);
            uint4 h0 = sh[0], h1 = sh[1], h2 = sh[2], h3 = sh[3];
            uint4 m0 = sm[0], m1 = sm[1], m2 = sm[2], m3 = sm[3];
            uint4 l0 = sl[0], l1 = sl[1], l2 = sl[2], l3 = sl[3];
            uint4* dh = reinterpret_cast<uint4*>(buf + BH_OFF + brow * RSTRIDE + bhalf * 64);
            uint4* dm = reinterpret_cast<uint4*>(buf + BM_OFF + brow * RSTRIDE + bhalf * 64);
            uint4* dl = reinterpret_cast<uint4*>(buf + BL_OFF + brow * RSTRIDE + bhalf * 64);
            dh[0] = h0; dh[1] = h1; dh[2] = h2; dh[3] = h3;
            dm[0] = m0; dm[1] = m1; dm[2] = m2; dm[3] = m3;
            dl[0] = l0; dl[1] = l1; dl[2] = l2; dl[3] = l3;
        }
        // ---- stage A: split row t (64 floats) into h/m/l bf16 ----
        {
            uint4* dh = reinterpret_cast<uint4*>(buf + AH_OFF + t * RSTRIDE);
            uint4* dm = reinterpret_cast<uint4*>(buf + AM_OFF + t * RSTRIDE);
            uint4* dl = reinterpret_cast<uint4*>(buf + AL_OFF + t * RSTRIDE);
#pragma unroll
            for (int g = 0; g < 8; g++) {
                float f[8] = { va[2 * g].x, va[2 * g].y, va[2 * g].z, va[2 * g].w,
                               va[2 * g + 1].x, va[2 * g + 1].y, va[2 * g + 1].z, va[2 * g + 1].w };
                __nv_bfloat16 h[8], m[8], l[8];
#pragma unroll
                for (int e = 0; e < 8; e++) {
                    srow += f[e] * f[e];
                    split3(f[e], h[e], m[e], l[e]);
                }
                dh[g] = make_uint4(packbf(h[0], h[1]), packbf(h[2], h[3]),
                                   packbf(h[4], h[5]), packbf(h[6], h[7]));
                dm[g] = make_uint4(packbf(m[0], m[1]), packbf(m[2], m[3]),
                                   packbf(m[4], m[5]), packbf(m[6], m[7]));
                dl[g] = make_uint4(packbf(l[0], l[1]), packbf(l[2], l[3]),
                                   packbf(l[4], l[5]), packbf(l[6], l[7]));
            }
        }
        __syncthreads();

        // ---- prefetch next A chunk ----
        if (c + 1 < NCHUNK) {
#pragma unroll
            for (int i = 0; i < 16; i++) va[i] = xrow[(c + 1) * 16 + i];
        }

        // ---- compute: 4 k16-steps ----
        const char* AH = buf + AH_OFF; const char* AM = buf + AM_OFF;
        const char* AL = buf + AL_OFF;
        const char* BH = buf + BH_OFF; const char* BM = buf + BM_OFF;
        const char* BL = buf + BL_OFF;
        const int M0 = wid * 32;
#pragma unroll
        for (int ks = 0; ks < 4; ks++) {
            const int kb = ks * 32 + 4 * cq;   // byte offset of this lane's k pair
            uint32_t af[2][3][4];
#pragma unroll
            for (int mt = 0; mt < 2; mt++) {
                const uint32_t base = (uint32_t)(M0 + mt * 16 + r) * RSTRIDE + kb;
                af[mt][0][0] = *(const uint32_t*)(AH + base);
                af[mt][0][1] = *(const uint32_t*)(AH + base + 8 * RSTRIDE);
                af[mt][0][2] = *(const uint32_t*)(AH + base + 16);
                af[mt][0][3] = *(const uint32_t*)(AH + base + 8 * RSTRIDE + 16);
                af[mt][1][0] = *(const uint32_t*)(AM + base);
                af[mt][1][1] = *(const uint32_t*)(AM + base + 8 * RSTRIDE);
                af[mt][1][2] = *(const uint32_t*)(AM + base + 16);
                af[mt][1][3] = *(const uint32_t*)(AM + base + 8 * RSTRIDE + 16);
                af[mt][2][0] = *(const uint32_t*)(AL + base);
                af[mt][2][1] = *(const uint32_t*)(AL + base + 8 * RSTRIDE);
                af[mt][2][2] = *(const uint32_t*)(AL + base + 16);
                af[mt][2][3] = *(const uint32_t*)(AL + base + 8 * RSTRIDE + 16);
            }
#pragma unroll
            for (int nt = 0; nt < 8; nt++) {
                const uint32_t bb = (uint32_t)(nt * 8 + r) * RSTRIDE + kb;
                uint32_t bh0 = *(const uint32_t*)(BH + bb);
                uint32_t bh1 = *(const uint32_t*)(BH + bb + 16);
                uint32_t bm0 = *(const uint32_t*)(BM + bb);
                uint32_t bm1 = *(const uint32_t*)(BM + bb + 16);
                uint32_t bl0 = *(const uint32_t*)(BL + bb);
                uint32_t bl1 = *(const uint32_t*)(BL + bb + 16);
#pragma unroll
                for (int mt = 0; mt < 2; mt++) {
                    float* d = acc[mt][nt];
                    mma_bf16(d, af[mt][0], bh0, bh1);   // h*h
                    mma_bf16(d, af[mt][0], bm0, bm1);   // h*m
                    mma_bf16(d, af[mt][1], bh0, bh1);   // m*h
                    mma_bf16(d, af[mt][1], bm0, bm1);   // m*m
                    mma_bf16(d, af[mt][0], bl0, bl1);   // h*l
                    mma_bf16(d, af[mt][2], bh0, bh1);   // l*h
                }
            }
        }
    }

    // ---- row norm (one row per thread; no reduction needed) ----
    inorm[t] = 1.0f / fmaxf(sqrtf(srow), 1e-8f);
    __syncthreads();

    // ---- epilogue: scale and store logits ----
#pragma unroll
    for (int mt = 0; mt < 2; mt++) {
        int row0 = wid * 32 + mt * 16 + r;
        float rn0 = inorm[row0], rn1 = inorm[row0 + 8];
        float* d0 = &g_logits[(blockRow + row0) * NEXP];
        float* d1 = &g_logits[(blockRow + row0 + 8) * NEXP];
#pragma unroll
        for (int nt = 0; nt < 8; nt++) {
            int col = nt * 8 + 2 * cq;
            *reinterpret_cast<float2*>(d0 + col) =
                make_float2(acc[mt][nt][0] * rn0, acc[mt][nt][1] * rn0);
            *reinterpret_cast<float2*>(d1 + col) =
                make_float2(acc[mt][nt][2] * rn1, acc[mt][nt][3] * rn1);
        }
    }
}

// ---------------------------------------------------------------------------
// Kernel 2: window-3 sum of logits, top-2 (tie -> lower index), renorm.
// ---------------------------------------------------------------------------
__device__ __forceinline__ bool better(float v, int vi, float w, int wi) {
    return (v > w) || (v == w && vi < wi);
}

__global__ void topk_kernel(float* __restrict__ out, int ntok, int out_size) {
    int warp = (blockIdx.x * blockDim.x + threadIdx.x) >> 5;
    int lane = threadIdx.x & 31;
    if (warp >= ntok) return;

    int b = warp / SEQ;
    int s = warp - b * SEQ;
    size_t t0 = (size_t)warp;
    size_t t1 = (size_t)b * SEQ + (s >= 1 ? s - 1 : 0);
    size_t t2 = (size_t)b * SEQ + (s >= 2 ? s - 2 : 0);

    float v0 = g_logits[t0 * NEXP + lane] + g_logits[t1 * NEXP + lane] +
               g_logits[t2 * NEXP + lane];
    float v1 = g_logits[t0 * NEXP + lane + 32] + g_logits[t1 * NEXP + lane + 32] +
               g_logits[t2 * NEXP + lane + 32];

    float a1, a2; int i1, i2;
    if (v0 >= v1) { a1 = v0; i1 = lane;      a2 = v1; i2 = lane + 32; }
    else          { a1 = v1; i1 = lane + 32; a2 = v0; i2 = lane;      }

#pragma unroll
    for (int off = 16; off; off >>= 1) {
        float ob1 = __shfl_xor_sync(0xffffffffu, a1, off);
        int   oj1 = __shfl_xor_sync(0xffffffffu, i1, off);
        float ob2 = __shfl_xor_sync(0xffffffffu, a2, off);
        int   oj2 = __shfl_xor_sync(0xffffffffu, i2, off);
        bool aw = better(a1, i1, ob1, oj1);
        float n1 = aw ? a1 : ob1;  int ni1 = aw ? i1 : oj1;
        float cc = aw ? ob1 : a1;  int ci  = aw ? oj1 : i1;
        float dd = aw ? a2 : ob2;  int di  = aw ? i2 : oj2;
        bool cw = better(cc, ci, dd, di);
        a1 = n1; i1 = ni1;
        a2 = cw ? cc : dd; i2 = cw ? ci : di;
    }

    if (lane == 0) {
        float e2 = expf((a2 - a1) * (1.0f / 3.0f));
        float inv = 1.0f / (1.0f + e2);
        if (out_size >= 4 * ntok) {
            out[t0 * 2 + 0] = (float)i1;
            out[t0 * 2 + 1] = (float)i2;
            out[(size_t)ntok * 2 + t0 * 2 + 0] = inv;
            out[(size_t)ntok * 2 + t0 * 2 + 1] = e2 * inv;
        } else if (out_size >= 2 * ntok) {
            out[t0 * 2 + 0] = (float)i1;
            out[t0 * 2 + 1] = (float)i2;
        }
    }
}

// ---------------------------------------------------------------------------
extern "C" void kernel_launch(void* const* d_in, const int* in_sizes, int n_in,
                              void* d_out, int out_size) {
    const float* x     = (const float*)d_in[0];
    const float* proto = (const float*)d_in[1];
    int ntok = in_sizes[2];
    if (ntok > MAXTOK) ntok = MAXTOK;
    float* out = (float*)d_out;

    cudaFuncSetAttribute(gemm_kernel,
                         cudaFuncAttributeMaxDynamicSharedMemorySize, SMEM_TOTAL);

    proto_split_kernel<<<(NEXP * DDIM + 255) / 256, 256>>>(proto);
    gemm_kernel<<<ntok / TM, NT, SMEM_TOTAL>>>(x);
    topk_kernel<<<(ntok + 7) / 8, 256>>>(out, ntok, out_size);
}

// round 9
// speedup vs baseline: 1.2429x; 1.2429x over previous
#include <cuda_runtime.h>
#include <cuda_bf16.h>
#include <math.h>
#include <stdint.h>

// x[8,2048,1024] fp32, prototypes[64,1024] fp32, attn_mask[8,2048] int32.
#define DDIM 1024
#define NEXP 64
#define SEQ  2048
#define TM   128
#define KC   64
#define NCHUNK (DDIM / KC)
#define NT   256
#define MAXTOK 16384

// smem: padded rows of 144 B (36 words; 36 mod 32 = 4 -> every 8-row x 16B
// ldmatrix phase hits 32 distinct banks).
#define RSTRIDE 144
#define AH_OFF 0
#define AM_OFF 18432
#define AL_OFF 36864
#define BH_OFF 55296
#define BM_OFF 64512
#define BL_OFF 73728
#define BUFSZ  82944
#define SMEM_BUF0 1024
#define SMEM_TOTAL (SMEM_BUF0 + 2 * BUFSZ)   // 166912

__device__ float g_logits[MAXTOK * NEXP];

// ---------------- helpers ----------------
__device__ __forceinline__ void split3(float x, __nv_bfloat16& h,
                                       __nv_bfloat16& m, __nv_bfloat16& l) {
    h = __float2bfloat16(x);
    float r = x - __bfloat162float(h);
    m = __float2bfloat16(r);
    float r2 = r - __bfloat162float(m);
    l = __float2bfloat16(r2);
}
__device__ __forceinline__ uint32_t packbf(__nv_bfloat16 a, __nv_bfloat16 b) {
    __nv_bfloat162 v(a, b);
    return *reinterpret_cast<uint32_t*>(&v);
}
__device__ __forceinline__ void ldm4(uint32_t* r, const void* p) {
    uint32_t a = (uint32_t)__cvta_generic_to_shared(p);
    asm volatile("ldmatrix.sync.aligned.m8n8.x4.shared.b16 {%0,%1,%2,%3}, [%4];"
                 : "=r"(r[0]), "=r"(r[1]), "=r"(r[2]), "=r"(r[3]) : "r"(a));
}
__device__ __forceinline__ void mma_bf16(float* d, const uint32_t* a,
                                         uint32_t b0, uint32_t b1) {
    asm volatile(
        "mma.sync.aligned.m16n8k16.row.col.f32.bf16.bf16.f32 "
        "{%0,%1,%2,%3}, {%4,%5,%6,%7}, {%8,%9}, {%0,%1,%2,%3};"
        : "+f"(d[0]), "+f"(d[1]), "+f"(d[2]), "+f"(d[3])
        : "r"(a[0]), "r"(a[1]), "r"(a[2]), "r"(a[3]), "r"(b0), "r"(b1));
}

// ---------------------------------------------------------------------------
// GEMM: bf16x6 emulated-fp32 on tensor cores + fused row norm + inline
// prototype split. 128 tokens x 64 experts / CTA, 8 warps (warp = 16 rows).
// ---------------------------------------------------------------------------
__global__ __launch_bounds__(NT, 1) void gemm_kernel(const float* __restrict__ x,
                                                     const float* __restrict__ proto) {
    extern __shared__ char smem[];
    float* inorm = reinterpret_cast<float*>(smem);
    char* buf0 = smem + SMEM_BUF0;

    const int t = threadIdx.x;
    const int wid = t >> 5, lane = t & 31;
    const size_t blockRow = (size_t)blockIdx.x * TM;

    // staging maps
    const int arow = t >> 1, ahalf = t & 1;          // A: half-row per thread
    const int pe = t >> 2, pq = t & 3;               // P: 16 k-vals per thread
    const float4* xsrc = reinterpret_cast<const float4*>(
        x + (blockRow + arow) * DDIM + ahalf * 32);
    const float4* psrc = reinterpret_cast<const float4*>(
        proto + (size_t)pe * DDIM + pq * 16);

    float acc[8][4];
#pragma unroll
    for (int j = 0; j < 8; j++)
#pragma unroll
        for (int q = 0; q < 4; q++) acc[j][q] = 0.f;

    float srow = 0.f;
    float4 va[8], vp[4];

    // compute-phase lane addressing
    const int M0 = wid * 16;
    const uint32_t a_off = (uint32_t)(M0 + (lane & 15)) * RSTRIDE + ((lane >> 4) << 4);
    const uint32_t b_n   = (lane & 7) + ((lane >> 4) << 3);
    const uint32_t b_kb  = ((lane >> 3) & 1) << 4;

    // prefetch chunk 0
#pragma unroll
    for (int i = 0; i < 8; i++) va[i] = xsrc[i];
#pragma unroll
    for (int i = 0; i < 4; i++) vp[i] = psrc[i];

    for (int c = 0; c < NCHUNK; c++) {
        char* buf = buf0 + (c & 1) * BUFSZ;

        // ---- stage A: split 32 floats into h/m/l ----
        {
            const uint32_t ad = (uint32_t)arow * RSTRIDE + ahalf * 64;
#pragma unroll
            for (int g = 0; g < 4; g++) {
                float f[8] = { va[2 * g].x, va[2 * g].y, va[2 * g].z, va[2 * g].w,
                               va[2 * g + 1].x, va[2 * g + 1].y,
                               va[2 * g + 1].z, va[2 * g + 1].w };
                __nv_bfloat16 h[8], m[8], l[8];
#pragma unroll
                for (int e = 0; e < 8; e++) {
                    srow += f[e] * f[e];
                    split3(f[e], h[e], m[e], l[e]);
                }
                *reinterpret_cast<uint4*>(buf + AH_OFF + ad + g * 16) =
                    make_uint4(packbf(h[0], h[1]), packbf(h[2], h[3]),
                               packbf(h[4], h[5]), packbf(h[6], h[7]));
                *reinterpret_cast<uint4*>(buf + AM_OFF + ad + g * 16) =
                    make_uint4(packbf(m[0], m[1]), packbf(m[2], m[3]),
                               packbf(m[4], m[5]), packbf(m[6], m[7]));
                *reinterpret_cast<uint4*>(buf + AL_OFF + ad + g * 16) =
                    make_uint4(packbf(l[0], l[1]), packbf(l[2], l[3]),
                               packbf(l[4], l[5]), packbf(l[6], l[7]));
            }
        }
        // ---- stage B: split 16 proto floats ----
        {
            const uint32_t pd = (uint32_t)pe * RSTRIDE + pq * 32;
            float f[16] = { vp[0].x, vp[0].y, vp[0].z, vp[0].w,
                            vp[1].x, vp[1].y, vp[1].z, vp[1].w,
                            vp[2].x, vp[2].y, vp[2].z, vp[2].w,
                            vp[3].x, vp[3].y, vp[3].z, vp[3].w };
            __nv_bfloat16 h[16], m[16], l[16];
#pragma unroll
            for (int e = 0; e < 16; e++) split3(f[e], h[e], m[e], l[e]);
#pragma unroll
            for (int half = 0; half < 2; half++) {
                int o = half * 8;
                *reinterpret_cast<uint4*>(buf + BH_OFF + pd + half * 16) =
                    make_uint4(packbf(h[o], h[o + 1]), packbf(h[o + 2], h[o + 3]),
                               packbf(h[o + 4], h[o + 5]), packbf(h[o + 6], h[o + 7]));
                *reinterpret_cast<uint4*>(buf + BM_OFF + pd + half * 16) =
                    make_uint4(packbf(m[o], m[o + 1]), packbf(m[o + 2], m[o + 3]),
                               packbf(m[o + 4], m[o + 5]), packbf(m[o + 6], m[o + 7]));
                *reinterpret_cast<uint4*>(buf + BL_OFF + pd + half * 16) =
                    make_uint4(packbf(l[o], l[o + 1]), packbf(l[o + 2], l[o + 3]),
                               packbf(l[o + 4], l[o + 5]), packbf(l[o + 6], l[o + 7]));
            }
        }
        __syncthreads();

        // ---- prefetch next chunk ----
        if (c + 1 < NCHUNK) {
#pragma unroll
            for (int i = 0; i < 8; i++) va[i] = xsrc[(c + 1) * 16 + i];
#pragma unroll
            for (int i = 0; i < 4; i++) vp[i] = psrc[(c + 1) * 16 + i];
        }

        // ---- compute: 4 k16-steps, ldmatrix fragments, 6-term MMAs ----
#pragma unroll
        for (int ks = 0; ks < 4; ks++) {
            const uint32_t ksb = ks * 32;
            uint32_t ah[4], am[4], al[4];
            ldm4(ah, buf + AH_OFF + a_off + ksb);
            ldm4(am, buf + AM_OFF + a_off + ksb);
            ldm4(al, buf + AL_OFF + a_off + ksb);
#pragma unroll
            for (int ntp = 0; ntp < 4; ntp++) {
                const uint32_t bo = (uint32_t)(ntp * 16 + b_n) * RSTRIDE + b_kb + ksb;
                uint32_t bh[4], bm[4], bl[4];
                ldm4(bh, buf + BH_OFF + bo);
                ldm4(bm, buf + BM_OFF + bo);
                ldm4(bl, buf + BL_OFF + bo);
#pragma unroll
                for (int j = 0; j < 2; j++) {
                    float* d = acc[ntp * 2 + j];
                    mma_bf16(d, ah, bh[2 * j], bh[2 * j + 1]);   // h*h
                    mma_bf16(d, ah, bm[2 * j], bm[2 * j + 1]);   // h*m
                    mma_bf16(d, am, bh[2 * j], bh[2 * j + 1]);   // m*h
                    mma_bf16(d, am, bm[2 * j], bm[2 * j + 1]);   // m*m
                    mma_bf16(d, ah, bl[2 * j], bl[2 * j + 1]);   // h*l
                    mma_bf16(d, al, bh[2 * j], bh[2 * j + 1]);   // l*h
                }
            }
        }
    }

    // ---- row norm: pair-combine (thread t, t^1 share row), write smem ----
    srow += __shfl_xor_sync(0xffffffffu, srow, 1);
    if ((t & 1) == 0) inorm[arow] = 1.0f / fmaxf(sqrtf(srow), 1e-8f);
    __syncthreads();

    // ---- epilogue: scale and store logits ----
    {
        const int g = lane >> 2, cq2 = 2 * (lane & 3);
        const int row0 = M0 + g;
        const float rn0 = inorm[row0], rn1 = inorm[row0 + 8];
        float* d0 = &g_logits[(blockRow + row0) * NEXP];
        float* d1 = &g_logits[(blockRow + row0 + 8) * NEXP];
#pragma unroll
        for (int nt = 0; nt < 8; nt++) {
            int col = nt * 8 + cq2;
            *reinterpret_cast<float2*>(d0 + col) =
                make_float2(acc[nt][0] * rn0, acc[nt][1] * rn0);
            *reinterpret_cast<float2*>(d1 + col) =
                make_float2(acc[nt][2] * rn1, acc[nt][3] * rn1);
        }
    }
}

// ---------------------------------------------------------------------------
// Topk: one thread per token. Serial top-2 scan (ties keep lower index),
// window-3 sum fused from three logit rows.
// ---------------------------------------------------------------------------
__global__ void topk_kernel(float* __restrict__ out, int ntok, int out_size) {
    int tok = blockIdx.x * blockDim.x + threadIdx.x;
    if (tok >= ntok) return;
    int b = tok / SEQ, s = tok - b * SEQ;
    const float4* r0 = reinterpret_cast<const float4*>(&g_logits[(size_t)tok * NEXP]);
    const float4* r1 = reinterpret_cast<const float4*>(
        &g_logits[((size_t)b * SEQ + (s >= 1 ? s - 1 : 0)) * NEXP]);
    const float4* r2 = reinterpret_cast<const float4*>(
        &g_logits[((size_t)b * SEQ + (s >= 2 ? s - 2 : 0)) * NEXP]);

    float a1 = -1e30f, a2 = -1e30f;
    int i1 = 0, i2 = 0;
#pragma unroll
    for (int g = 0; g < 16; g++) {
        float4 u = r0[g], v = r1[g], w = r2[g];
        float sv[4] = { u.x + v.x + w.x, u.y + v.y + w.y,
                        u.z + v.z + w.z, u.w + v.w + w.w };
#pragma unroll
        for (int e = 0; e < 4; e++) {
            float val = sv[e];
            int idx = 4 * g + e;
            if (val > a1) { a2 = a1; i2 = i1; a1 = val; i1 = idx; }
            else if (val > a2) { a2 = val; i2 = idx; }
        }
    }

    float e2 = expf((a2 - a1) * (1.0f / 3.0f));
    float inv = 1.0f / (1.0f + e2);
    size_t t0 = (size_t)tok;
    if (out_size >= 4 * ntok) {
        out[t0 * 2 + 0] = (float)i1;
        out[t0 * 2 + 1] = (float)i2;
        out[(size_t)ntok * 2 + t0 * 2 + 0] = inv;
        out[(size_t)ntok * 2 + t0 * 2 + 1] = e2 * inv;
    } else if (out_size >= 2 * ntok) {
        out[t0 * 2 + 0] = (float)i1;
        out[t0 * 2 + 1] = (float)i2;
    }
}

// ---------------------------------------------------------------------------
extern "C" void kernel_launch(void* const* d_in, const int* in_sizes, int n_in,
                              void* d_out, int out_size) {
    const float* x     = (const float*)d_in[0];
    const float* proto = (const float*)d_in[1];
    int ntok = in_sizes[2];
    if (ntok > MAXTOK) ntok = MAXTOK;
    float* out = (float*)d_out;

    cudaFuncSetAttribute(gemm_kernel,
                         cudaFuncAttributeMaxDynamicSharedMemorySize, SMEM_TOTAL);

    gemm_kernel<<<ntok / TM, NT, SMEM_TOTAL>>>(x, proto);
    topk_kernel<<<(ntok + 127) / 128, 128>>>(out, ntok, out_size);
}